// round 2
// baseline (speedup 1.0000x reference)
#include <cuda_runtime.h>

typedef unsigned long long u64;

#define NPOS (4096*128)
#define TILE 128
#define NTILES (NPOS/TILE)      // 4096
#define THREADS 512
#define NBLOCKS 1024

// ---- packed fp32x2 helpers (sm_103a) ----
static __device__ __forceinline__ u64 fma2(u64 a, u64 b, u64 c) {
    u64 d;
    asm("fma.rn.f32x2 %0, %1, %2, %3;" : "=l"(d) : "l"(a), "l"(b), "l"(c));
    return d;
}
union F2 { u64 u; float2 f; };
static __device__ __forceinline__ u64 dup2(float x) { F2 t; t.f.x = x; t.f.y = x; return t.u; }

struct __align__(16) Smem {
    float  X[3][TILE];       // input tile
    float  Val[TILE];        // validity mask
    float4 W1[64];           // folded layer1: a0,a1,a2,c
    float  C2[64];
    float  C3[128];
    float  Inv2[64];
    float  Inv3[128];
    float  W2D[64][128];     // [k][2*o] duplicated pairs (folded)
    float  W3D[64][256];     // [k][2*o] duplicated pairs (folded)
    float  Y1[64][TILE];
    float  Y2[64][TILE];
};

extern "C" __global__ void __launch_bounds__(THREADS, 1)
pn_fused_kernel(const float* __restrict__ pc,  const float* __restrict__ valid,
                const float* __restrict__ W1,  const float* __restrict__ b1,
                const float* __restrict__ g1,  const float* __restrict__ be1,
                const float* __restrict__ m1,  const float* __restrict__ v1,
                const float* __restrict__ W2,  const float* __restrict__ b2,
                const float* __restrict__ g2,  const float* __restrict__ be2,
                const float* __restrict__ m2,  const float* __restrict__ v2,
                const float* __restrict__ W3,  const float* __restrict__ b3,
                const float* __restrict__ g3,  const float* __restrict__ be3,
                const float* __restrict__ m3,  const float* __restrict__ v3,
                float* __restrict__ out)
{
    extern __shared__ char smem_raw[];
    Smem& s = *reinterpret_cast<Smem*>(smem_raw);
    const int t = threadIdx.x;

    // ---- fold BN into weights (once per block) ----
    if (t < 64) {
        float inv1 = g1[t] * rsqrtf(v1[t] + 1e-5f);
        s.W1[t] = make_float4(W1[3*t+0]*inv1, W1[3*t+1]*inv1, W1[3*t+2]*inv1,
                              be1[t] + (b1[t] - m1[t]) * inv1);
        float inv2 = g2[t] * rsqrtf(v2[t] + 1e-5f);
        s.Inv2[t] = inv2;
        s.C2[t]   = be2[t] + (b2[t] - m2[t]) * inv2;
    }
    if (t < 128) {
        float inv3 = g3[t] * rsqrtf(v3[t] + 1e-5f);
        s.Inv3[t] = inv3;
        s.C3[t]   = be3[t] + (b3[t] - m3[t]) * inv3;
    }
    __syncthreads();
    for (int i = t; i < 64*64; i += THREADS) {
        int o = i >> 6, k = i & 63;
        float w = W2[i] * s.Inv2[o];
        *reinterpret_cast<u64*>(&s.W2D[k][2*o]) = dup2(w);
    }
    for (int i = t; i < 128*64; i += THREADS) {
        int o = i >> 6, k = i & 63;
        float w = W3[i] * s.Inv3[o];
        *reinterpret_cast<u64*>(&s.W3D[k][2*o]) = dup2(w);
    }

    const int cg = t & 15;       // column group (8 cols each)
    const int rg = t >> 4;       // row group: 0..31
    const int c0 = cg * 8;

    for (int tile = blockIdx.x; tile < NTILES; tile += gridDim.x) {
        const int p0 = tile * TILE;
        __syncthreads();   // protects weight fill (iter 0) and X/Val/Y reuse (iter >0)

        // ---- stage 0: load X tile + valid ----
        if (t < 3*TILE) {
            int ch = t >> 7, p = t & 127;
            s.X[ch][p] = pc[(size_t)ch * NPOS + p0 + p];
        }
        if (t >= 384 && t < 384 + TILE) s.Val[t - 384] = valid[p0 + (t - 384)];
        __syncthreads();

        // ---- layer 1: Y1[64][128] = relu(A1 * X + c1) ----
        {
            int p = t & 127, q = t >> 7;     // q in 0..3 -> 16 channels each
            float x0 = s.X[0][p], x1 = s.X[1][p], x2 = s.X[2][p];
            #pragma unroll
            for (int j = 0; j < 16; ++j) {
                int ch = q * 16 + j;
                float4 w = s.W1[ch];
                float y = fmaf(w.x, x0, fmaf(w.y, x1, fmaf(w.z, x2, w.w)));
                s.Y1[ch][p] = fmaxf(y, 0.f);
            }
        }
        __syncthreads();

        // ---- layer 2: Y2[64][128] = relu(A2 * Y1 + c2) ----
        {
            const int r0 = rg * 2;  // rows r0..r0+1
            u64 acc[2][4];
            #pragma unroll
            for (int i = 0; i < 2; ++i) {
                u64 d = dup2(s.C2[r0 + i]);
                acc[i][0] = d; acc[i][1] = d; acc[i][2] = d; acc[i][3] = d;
            }
            #pragma unroll 4
            for (int k = 0; k < 64; ++k) {
                ulonglong2 A0 = *reinterpret_cast<const ulonglong2*>(&s.W2D[k][2*r0]);
                const ulonglong2* bw = reinterpret_cast<const ulonglong2*>(&s.Y1[k][c0]);
                ulonglong2 B0 = bw[0], B1 = bw[1];
                u64 a[2] = {A0.x, A0.y};
                u64 b[4] = {B0.x, B0.y, B1.x, B1.y};
                #pragma unroll
                for (int i = 0; i < 2; ++i)
                    #pragma unroll
                    for (int j = 0; j < 4; ++j)
                        acc[i][j] = fma2(a[i], b[j], acc[i][j]);
            }
            #pragma unroll
            for (int i = 0; i < 2; ++i) {
                float r[8];
                #pragma unroll
                for (int j = 0; j < 4; ++j) {
                    F2 q; q.u = acc[i][j];
                    r[2*j+0] = fmaxf(q.f.x, 0.f);
                    r[2*j+1] = fmaxf(q.f.y, 0.f);
                }
                *reinterpret_cast<float4*>(&s.Y2[r0+i][c0])   = make_float4(r[0], r[1], r[2], r[3]);
                *reinterpret_cast<float4*>(&s.Y2[r0+i][c0+4]) = make_float4(r[4], r[5], r[6], r[7]);
            }
        }
        __syncthreads();

        // ---- layer 3: out[128][128] = relu(A3 * Y2 + c3) * valid ----
        {
            const int R0 = rg * 4;  // rows R0..R0+3 of 128
            u64 acc[4][4];
            #pragma unroll
            for (int i = 0; i < 4; ++i) {
                u64 d = dup2(s.C3[R0 + i]);
                acc[i][0] = d; acc[i][1] = d; acc[i][2] = d; acc[i][3] = d;
            }
            #pragma unroll 4
            for (int k = 0; k < 64; ++k) {
                const ulonglong2* aw = reinterpret_cast<const ulonglong2*>(&s.W3D[k][2*R0]);
                ulonglong2 A0 = aw[0], A1 = aw[1];
                const ulonglong2* bw = reinterpret_cast<const ulonglong2*>(&s.Y2[k][c0]);
                ulonglong2 B0 = bw[0], B1 = bw[1];
                u64 a[4] = {A0.x, A0.y, A1.x, A1.y};
                u64 b[4] = {B0.x, B0.y, B1.x, B1.y};
                #pragma unroll
                for (int i = 0; i < 4; ++i)
                    #pragma unroll
                    for (int j = 0; j < 4; ++j)
                        acc[i][j] = fma2(a[i], b[j], acc[i][j]);
            }
            // epilogue: relu, mask, store
            float v[8];
            #pragma unroll
            for (int j = 0; j < 8; ++j) v[j] = s.Val[c0 + j];
            #pragma unroll
            for (int i = 0; i < 4; ++i) {
                float r[8];
                #pragma unroll
                for (int j = 0; j < 4; ++j) {
                    F2 q; q.u = acc[i][j];
                    r[2*j+0] = fmaxf(q.f.x, 0.f) * v[2*j+0];
                    r[2*j+1] = fmaxf(q.f.y, 0.f) * v[2*j+1];
                }
                float* dst = out + (size_t)(R0 + i) * NPOS + p0 + c0;
                *reinterpret_cast<float4*>(dst)     = make_float4(r[0], r[1], r[2], r[3]);
                *reinterpret_cast<float4*>(dst + 4) = make_float4(r[4], r[5], r[6], r[7]);
            }
        }
    }
}

extern "C" void kernel_launch(void* const* d_in, const int* in_sizes, int n_in,
                              void* d_out, int out_size)
{
    (void)in_sizes; (void)n_in; (void)out_size;
    cudaFuncSetAttribute(pn_fused_kernel,
                         cudaFuncAttributeMaxDynamicSharedMemorySize,
                         (int)sizeof(Smem));
    pn_fused_kernel<<<NBLOCKS, THREADS, sizeof(Smem)>>>(
        (const float*)d_in[0],  (const float*)d_in[1],
        (const float*)d_in[2],  (const float*)d_in[3],  (const float*)d_in[4],
        (const float*)d_in[5],  (const float*)d_in[6],  (const float*)d_in[7],
        (const float*)d_in[8],  (const float*)d_in[9],  (const float*)d_in[10],
        (const float*)d_in[11], (const float*)d_in[12], (const float*)d_in[13],
        (const float*)d_in[14], (const float*)d_in[15], (const float*)d_in[16],
        (const float*)d_in[17], (const float*)d_in[18], (const float*)d_in[19],
        (float*)d_out);
}

// round 4
// speedup vs baseline: 3.7869x; 3.7869x over previous
#include <cuda_runtime.h>
#include <cuda_fp16.h>
#include <cstdint>

typedef uint32_t u32;

#define NPOS    (4096*128)
#define NTILES  4096
#define THREADS 256
#define NBLOCKS 296

// ---- dynamic SMEM layout (bytes) ----
#define SM_W1F  0          // 64 x float4            (1024)
#define SM_C2   1024       // 64 floats              (256)
#define SM_C3   1280       // 128 floats             (512)
#define SM_VAL  1792       // 128 floats             (512)
#define SM_Y1   2304       // 128 rows x 72 halves   (18432)
#define SM_Y2   20736      // 128 x 72               (18432)
#define SM_W2   39168      // 64  x 72               (9216)
#define SM_W3   48384      // 128 x 72               (18432)
#define SMEM_TOTAL 66816

#define RSTRIDE 72         // halves per row (144 B, conflict-free & 16B aligned)

static __device__ __forceinline__ u32 sptr(const void* p) {
    u32 a;
    asm("{ .reg .u64 t; cvta.to.shared.u64 t, %1; cvt.u32.u64 %0, t; }" : "=r"(a) : "l"(p));
    return a;
}
static __device__ __forceinline__ void ldm4(u32& r0, u32& r1, u32& r2, u32& r3, u32 addr) {
    asm volatile("ldmatrix.sync.aligned.m8n8.x4.shared.b16 {%0,%1,%2,%3}, [%4];"
                 : "=r"(r0), "=r"(r1), "=r"(r2), "=r"(r3) : "r"(addr));
}
static __device__ __forceinline__ void ldm2(u32& r0, u32& r1, u32 addr) {
    asm volatile("ldmatrix.sync.aligned.m8n8.x2.shared.b16 {%0,%1}, [%2];"
                 : "=r"(r0), "=r"(r1) : "r"(addr));
}
static __device__ __forceinline__ void mma16816(float c[4], const u32 a[4], const u32 b[2]) {
    asm volatile("mma.sync.aligned.m16n8k16.row.col.f32.f16.f16.f32 "
                 "{%0,%1,%2,%3}, {%4,%5,%6,%7}, {%8,%9}, {%0,%1,%2,%3};"
                 : "+f"(c[0]), "+f"(c[1]), "+f"(c[2]), "+f"(c[3])
                 : "r"(a[0]), "r"(a[1]), "r"(a[2]), "r"(a[3]), "r"(b[0]), "r"(b[1]));
}
static __device__ __forceinline__ u32 pack2(float a, float b) {
    __half2 h = __floats2half2_rn(a, b);
    return *reinterpret_cast<u32*>(&h);
}

extern "C" __global__ void __launch_bounds__(THREADS, 2)
pn_mma_kernel(const float* __restrict__ pc,  const float* __restrict__ valid,
              const float* __restrict__ W1,  const float* __restrict__ b1,
              const float* __restrict__ g1,  const float* __restrict__ be1,
              const float* __restrict__ m1,  const float* __restrict__ v1,
              const float* __restrict__ W2,  const float* __restrict__ b2,
              const float* __restrict__ g2,  const float* __restrict__ be2,
              const float* __restrict__ m2,  const float* __restrict__ v2,
              const float* __restrict__ W3,  const float* __restrict__ b3,
              const float* __restrict__ g3,  const float* __restrict__ be3,
              const float* __restrict__ m3,  const float* __restrict__ v3,
              float* __restrict__ out)
{
    extern __shared__ char smem[];
    const u32 sb = sptr(smem);
    const int t    = threadIdx.x;
    const int lane = t & 31;
    const int w    = t >> 5;
    const int mg   = w & 1;        // M half (64 rows)
    const int ng   = w >> 1;       // N quarter

    float*  s_w1f = reinterpret_cast<float*>(smem + SM_W1F);
    float*  s_c2  = reinterpret_cast<float*>(smem + SM_C2);
    float*  s_c3  = reinterpret_cast<float*>(smem + SM_C3);
    float*  s_val = reinterpret_cast<float*>(smem + SM_VAL);
    __half* s_w2  = reinterpret_cast<__half*>(smem + SM_W2);
    __half* s_w3  = reinterpret_cast<__half*>(smem + SM_W3);
    __half* s_y1  = reinterpret_cast<__half*>(smem + SM_Y1);
    __half* s_y2  = reinterpret_cast<__half*>(smem + SM_Y2);

    // ---- one-time prep: fold BN, convert weights to fp16 ----
    if (t < 64) {
        float inv1 = g1[t] * rsqrtf(v1[t] + 1e-5f);
        s_w1f[4*t+0] = W1[3*t+0]*inv1;
        s_w1f[4*t+1] = W1[3*t+1]*inv1;
        s_w1f[4*t+2] = W1[3*t+2]*inv1;
        s_w1f[4*t+3] = be1[t] + (b1[t] - m1[t]) * inv1;
        float inv2 = g2[t] * rsqrtf(v2[t] + 1e-5f);
        s_c2[t] = be2[t] + (b2[t] - m2[t]) * inv2;
    }
    if (t < 128) {
        float inv3 = g3[t] * rsqrtf(v3[t] + 1e-5f);
        s_c3[t] = be3[t] + (b3[t] - m3[t]) * inv3;
    }
    for (int i = t; i < 64*64; i += THREADS) {
        int n = i >> 6, k = i & 63;
        float inv2 = g2[n] * rsqrtf(v2[n] + 1e-5f);
        s_w2[n*RSTRIDE + k] = __float2half_rn(W2[i] * inv2);
    }
    for (int i = t; i < 128*64; i += THREADS) {
        int n = i >> 6, k = i & 63;
        float inv3 = g3[n] * rsqrtf(v3[n] + 1e-5f);
        s_w3[n*RSTRIDE + k] = __float2half_rn(W3[i] * inv3);
    }
    __syncthreads();

    // ---- per-warp ldmatrix base addresses ----
    const int lr8 = (lane & 7) + ((lane >> 3) & 1) * 8;  // x4 row-in-16
    const int lc8 = (lane >> 4) * 8;                     // x4 k offset 0/8
    const int br  = lane & 7;                            // x2 row
    const int bc8 = ((lane >> 3) & 1) * 8;               // x2 k offset 0/8
    const int qr  = lane >> 2;                           // accum row in 8
    const int qc  = (lane & 3) * 2;                      // accum col pair

    u32 a2b[4], a3b[4], b2b[2], b3b[4];
    #pragma unroll
    for (int mt = 0; mt < 4; ++mt) {
        a2b[mt] = sb + SM_Y1 + ((mg*64 + mt*16 + lr8)*RSTRIDE + lc8)*2;
        a3b[mt] = sb + SM_W3 + ((mg*64 + mt*16 + lr8)*RSTRIDE + lc8)*2;
    }
    #pragma unroll
    for (int nt = 0; nt < 2; ++nt)
        b2b[nt] = sb + SM_W2 + ((ng*16 + nt*8 + br)*RSTRIDE + bc8)*2;
    #pragma unroll
    for (int nt = 0; nt < 4; ++nt)
        b3b[nt] = sb + SM_Y2 + ((ng*32 + nt*8 + br)*RSTRIDE + bc8)*2;

    const int p  = t & 127;        // position within tile (for layer1)
    const int hf = t >> 7;         // channel half for layer1
    const u32 y1row = sb + SM_Y1 + (p*RSTRIDE + hf*32)*2;

    for (int tile = blockIdx.x; tile < NTILES; tile += gridDim.x) {
        const int p0 = tile * 128;

        // ---- layer 1: fp32 -> relu -> fp16 Y1[pos][k] ----
        {
            float x0 = pc[p0 + p], x1 = pc[NPOS + p0 + p], x2 = pc[2*NPOS + p0 + p];
            if (t < 128) s_val[t] = valid[p0 + t];
            #pragma unroll
            for (int cb = 0; cb < 32; cb += 8) {
                u32 pk[4];
                #pragma unroll
                for (int q = 0; q < 4; ++q) {
                    int c0i = hf*32 + cb + 2*q;
                    float ya = fmaf(s_w1f[4*c0i+0], x0, fmaf(s_w1f[4*c0i+1], x1,
                               fmaf(s_w1f[4*c0i+2], x2, s_w1f[4*c0i+3])));
                    float yb = fmaf(s_w1f[4*c0i+4], x0, fmaf(s_w1f[4*c0i+5], x1,
                               fmaf(s_w1f[4*c0i+6], x2, s_w1f[4*c0i+7])));
                    pk[q] = pack2(fmaxf(ya, 0.f), fmaxf(yb, 0.f));
                }
                asm volatile("st.shared.v4.b32 [%0], {%1,%2,%3,%4};"
                             :: "r"(y1row + cb*2), "r"(pk[0]), "r"(pk[1]), "r"(pk[2]), "r"(pk[3])
                             : "memory");
            }
        }
        __syncthreads();

        // ---- layer 2: acc[pos 64][out 16] ----
        {
            float acc[4][2][4];
            float2 bias[2];
            #pragma unroll
            for (int nt = 0; nt < 2; ++nt)
                bias[nt] = *reinterpret_cast<const float2*>(&s_c2[ng*16 + nt*8 + qc]);
            #pragma unroll
            for (int mt = 0; mt < 4; ++mt)
                #pragma unroll
                for (int nt = 0; nt < 2; ++nt) {
                    acc[mt][nt][0] = bias[nt].x; acc[mt][nt][1] = bias[nt].y;
                    acc[mt][nt][2] = bias[nt].x; acc[mt][nt][3] = bias[nt].y;
                }
            #pragma unroll
            for (int kt = 0; kt < 4; ++kt) {
                u32 a[4][4], b[2][2];
                #pragma unroll
                for (int mt = 0; mt < 4; ++mt)
                    ldm4(a[mt][0], a[mt][1], a[mt][2], a[mt][3], a2b[mt] + kt*32);
                #pragma unroll
                for (int nt = 0; nt < 2; ++nt)
                    ldm2(b[nt][0], b[nt][1], b2b[nt] + kt*32);
                #pragma unroll
                for (int mt = 0; mt < 4; ++mt)
                    #pragma unroll
                    for (int nt = 0; nt < 2; ++nt)
                        mma16816(acc[mt][nt], a[mt], b[nt]);
            }
            // epilogue: relu -> fp16 -> Y2[pos][k]
            #pragma unroll
            for (int mt = 0; mt < 4; ++mt)
                #pragma unroll
                for (int nt = 0; nt < 2; ++nt) {
                    int row = mg*64 + mt*16 + qr;
                    int col = ng*16 + nt*8 + qc;
                    u32 h01 = pack2(fmaxf(acc[mt][nt][0], 0.f), fmaxf(acc[mt][nt][1], 0.f));
                    u32 h23 = pack2(fmaxf(acc[mt][nt][2], 0.f), fmaxf(acc[mt][nt][3], 0.f));
                    *reinterpret_cast<u32*>(&s_y2[row*RSTRIDE + col])       = h01;
                    *reinterpret_cast<u32*>(&s_y2[(row + 8)*RSTRIDE + col]) = h23;
                }
        }
        __syncthreads();

        // ---- layer 3: acc[out 64][pos 32] ----
        {
            float acc[4][4][4];
            #pragma unroll
            for (int mt = 0; mt < 4; ++mt) {
                float bm0 = s_c3[mg*64 + mt*16 + qr];
                float bm8 = s_c3[mg*64 + mt*16 + qr + 8];
                #pragma unroll
                for (int nt = 0; nt < 4; ++nt) {
                    acc[mt][nt][0] = bm0; acc[mt][nt][1] = bm0;
                    acc[mt][nt][2] = bm8; acc[mt][nt][3] = bm8;
                }
            }
            #pragma unroll
            for (int kt = 0; kt < 4; ++kt) {
                u32 a[4][4], b[4][2];
                #pragma unroll
                for (int mt = 0; mt < 4; ++mt)
                    ldm4(a[mt][0], a[mt][1], a[mt][2], a[mt][3], a3b[mt] + kt*32);
                #pragma unroll
                for (int nt = 0; nt < 4; ++nt)
                    ldm2(b[nt][0], b[nt][1], b3b[nt] + kt*32);
                #pragma unroll
                for (int mt = 0; mt < 4; ++mt)
                    #pragma unroll
                    for (int nt = 0; nt < 4; ++nt)
                        mma16816(acc[mt][nt], a[mt], b[nt]);
            }
            // epilogue: relu * valid -> out[channel][pos]
            #pragma unroll
            for (int nt = 0; nt < 4; ++nt) {
                int pcol = ng*32 + nt*8 + qc;
                float2 vv = *reinterpret_cast<const float2*>(&s_val[pcol]);
                #pragma unroll
                for (int mt = 0; mt < 4; ++mt) {
                    int m = mg*64 + mt*16 + qr;
                    float2 o0, o1;
                    o0.x = fmaxf(acc[mt][nt][0], 0.f) * vv.x;
                    o0.y = fmaxf(acc[mt][nt][1], 0.f) * vv.y;
                    o1.x = fmaxf(acc[mt][nt][2], 0.f) * vv.x;
                    o1.y = fmaxf(acc[mt][nt][3], 0.f) * vv.y;
                    *reinterpret_cast<float2*>(out + (size_t)m*NPOS + p0 + pcol)       = o0;
                    *reinterpret_cast<float2*>(out + (size_t)(m + 8)*NPOS + p0 + pcol) = o1;
                }
            }
        }
        __syncthreads();
    }
}

extern "C" void kernel_launch(void* const* d_in, const int* in_sizes, int n_in,
                              void* d_out, int out_size)
{
    (void)in_sizes; (void)n_in; (void)out_size;
    cudaFuncSetAttribute(pn_mma_kernel,
                         cudaFuncAttributeMaxDynamicSharedMemorySize, SMEM_TOTAL);
    pn_mma_kernel<<<NBLOCKS, THREADS, SMEM_TOTAL>>>(
        (const float*)d_in[0],  (const float*)d_in[1],
        (const float*)d_in[2],  (const float*)d_in[3],  (const float*)d_in[4],
        (const float*)d_in[5],  (const float*)d_in[6],  (const float*)d_in[7],
        (const float*)d_in[8],  (const float*)d_in[9],  (const float*)d_in[10],
        (const float*)d_in[11], (const float*)d_in[12], (const float*)d_in[13],
        (const float*)d_in[14], (const float*)d_in[15], (const float*)d_in[16],
        (const float*)d_in[17], (const float*)d_in[18], (const float*)d_in[19],
        (float*)d_out);
}

// round 6
// speedup vs baseline: 6.9832x; 1.8440x over previous
#include <cuda_runtime.h>
#include <cuda_fp16.h>
#include <cstdint>

typedef uint32_t u32;

#define NPOS    (4096*128)
#define NTILES  4096
#define THREADS 256
#define NBLOCKS 444

#define RSTRIDE 72         // halves per row (144 B, ldmatrix conflict-free)

// ---- dynamic SMEM layout (bytes) ----
#define SM_W1F  0          // 64 x float4                  (1024)
#define SM_C2   1024       // 64 f                         (256)
#define SM_C3   1280       // 128 f                        (512)
#define SM_VAL  1792       // 2 x 128 f (double-buffered)  (1024)
#define SM_Y1   2816       // 2 x 128 x 72 halves          (36864)
#define SM_W2   39680      // 64  x 72 halves              (9216)
#define SM_W3   48896      // 128 x 72 halves              (18432)
#define SMEM_TOTAL 67328
#define Y1_BUF  18432

static __device__ __forceinline__ u32 sptr(const void* p) {
    u32 a;
    asm("{ .reg .u64 t; cvta.to.shared.u64 t, %1; cvt.u32.u64 %0, t; }" : "=r"(a) : "l"(p));
    return a;
}
static __device__ __forceinline__ void ldm4(u32& r0, u32& r1, u32& r2, u32& r3, u32 addr) {
    asm volatile("ldmatrix.sync.aligned.m8n8.x4.shared.b16 {%0,%1,%2,%3}, [%4];"
                 : "=r"(r0), "=r"(r1), "=r"(r2), "=r"(r3) : "r"(addr));
}
static __device__ __forceinline__ void mma16816(float c[4], const u32 a[4], u32 b0, u32 b1) {
    asm volatile("mma.sync.aligned.m16n8k16.row.col.f32.f16.f16.f32 "
                 "{%0,%1,%2,%3}, {%4,%5,%6,%7}, {%8,%9}, {%0,%1,%2,%3};"
                 : "+f"(c[0]), "+f"(c[1]), "+f"(c[2]), "+f"(c[3])
                 : "r"(a[0]), "r"(a[1]), "r"(a[2]), "r"(a[3]), "r"(b0), "r"(b1));
}
static __device__ __forceinline__ u32 pack2(float a, float b) {
    __half2 h = __floats2half2_rn(a, b);
    return *reinterpret_cast<u32*>(&h);
}

extern "C" __global__ void __launch_bounds__(THREADS, 3)
pn_mma_kernel(const float* __restrict__ pc,  const float* __restrict__ valid,
              const float* __restrict__ W1,  const float* __restrict__ b1,
              const float* __restrict__ g1,  const float* __restrict__ be1,
              const float* __restrict__ m1,  const float* __restrict__ v1,
              const float* __restrict__ W2,  const float* __restrict__ b2,
              const float* __restrict__ g2,  const float* __restrict__ be2,
              const float* __restrict__ m2,  const float* __restrict__ v2,
              const float* __restrict__ W3,  const float* __restrict__ b3,
              const float* __restrict__ g3,  const float* __restrict__ be3,
              const float* __restrict__ m3,  const float* __restrict__ v3,
              float* __restrict__ out)
{
    extern __shared__ char smem[];
    const u32 sb = sptr(smem);
    const int t    = threadIdx.x;
    const int lane = t & 31;
    const int w    = t >> 5;

    float*  s_w1f = reinterpret_cast<float*>(smem + SM_W1F);
    float*  s_c2  = reinterpret_cast<float*>(smem + SM_C2);
    float*  s_c3  = reinterpret_cast<float*>(smem + SM_C3);
    float*  s_val = reinterpret_cast<float*>(smem + SM_VAL);
    __half* s_w2  = reinterpret_cast<__half*>(smem + SM_W2);
    __half* s_w3  = reinterpret_cast<__half*>(smem + SM_W3);

    // ---- one-time prep: fold BN, convert weights to fp16 ----
    if (t < 64) {
        float inv1 = g1[t] * rsqrtf(v1[t] + 1e-5f);
        s_w1f[4*t+0] = W1[3*t+0]*inv1;
        s_w1f[4*t+1] = W1[3*t+1]*inv1;
        s_w1f[4*t+2] = W1[3*t+2]*inv1;
        s_w1f[4*t+3] = be1[t] + (b1[t] - m1[t]) * inv1;
        float inv2 = g2[t] * rsqrtf(v2[t] + 1e-5f);
        s_c2[t] = be2[t] + (b2[t] - m2[t]) * inv2;
    }
    if (t < 128) {
        float inv3 = g3[t] * rsqrtf(v3[t] + 1e-5f);
        s_c3[t] = be3[t] + (b3[t] - m3[t]) * inv3;
    }
    for (int i = t; i < 64*64; i += THREADS) {
        int n = i >> 6, k = i & 63;
        float inv2 = g2[n] * rsqrtf(v2[n] + 1e-5f);
        s_w2[n*RSTRIDE + k] = __float2half_rn(W2[i] * inv2);
    }
    for (int i = t; i < 128*64; i += THREADS) {
        int n = i >> 6, k = i & 63;
        float inv3 = g3[n] * rsqrtf(v3[n] + 1e-5f);
        s_w3[n*RSTRIDE + k] = __float2half_rn(W3[i] * inv3);
    }
    __syncthreads();

    // ---- per-thread fragment geometry ----
    const int qr  = lane >> 2;            // accum row in 8
    const int qc  = (lane & 3) * 2;       // accum col pair
    const int lr8 = (lane & 7) + ((lane >> 3) & 1) * 8;  // ldm4 row-in-16
    const int lc8 = (lane >> 4) * 8;                     // ldm4 k offset

    const int p  = t & 127;               // layer1: position
    const int hf = t >> 7;                // layer1: channel half

    const u32 w2base = sb + SM_W2 + (u32)(((lane & 15)*RSTRIDE + lc8)*2);
    const u32 w3base = sb + SM_W3 + (u32)((lr8*RSTRIDE + lc8)*2);
    const u32 a2off  = (u32)(((w*16 + lr8)*RSTRIDE + lc8)*2);
    const u32 y1off  = (u32)((p*RSTRIDE + hf*32)*2);

    // ---- prefetch first tile ----
    int tile = blockIdx.x;
    float x0 = 0.f, x1 = 0.f, x2 = 0.f, vld = 0.f;
    if (tile < NTILES) {
        int px = tile*128 + p;
        x0 = pc[px]; x1 = pc[NPOS + px]; x2 = pc[2*NPOS + px];
        if (t < 128) vld = valid[tile*128 + t];
    }

    int it = 0;
    for (; tile < NTILES; tile += gridDim.x, ++it) {
        const int p0  = tile * 128;
        const int buf = it & 1;
        const u32 y1b = sb + SM_Y1 + (u32)buf * Y1_BUF;

        // ---- layer 1: fp32 -> relu -> fp16 Y1[pos][k] (buffered) ----
        {
            if (t < 128) s_val[buf*128 + t] = vld;
            const u32 dst = y1b + y1off;
            #pragma unroll
            for (int cb = 0; cb < 32; cb += 8) {
                u32 pk[4];
                #pragma unroll
                for (int q = 0; q < 4; ++q) {
                    int c0i = hf*32 + cb + 2*q;
                    float ya = fmaf(s_w1f[4*c0i+0], x0, fmaf(s_w1f[4*c0i+1], x1,
                               fmaf(s_w1f[4*c0i+2], x2, s_w1f[4*c0i+3])));
                    float yb = fmaf(s_w1f[4*c0i+4], x0, fmaf(s_w1f[4*c0i+5], x1,
                               fmaf(s_w1f[4*c0i+6], x2, s_w1f[4*c0i+7])));
                    pk[q] = pack2(fmaxf(ya, 0.f), fmaxf(yb, 0.f));
                }
                asm volatile("st.shared.v4.b32 [%0], {%1,%2,%3,%4};"
                             :: "r"(dst + cb*2), "r"(pk[0]), "r"(pk[1]), "r"(pk[2]), "r"(pk[3])
                             : "memory");
            }
        }
        __syncthreads();

        // ---- prefetch next tile (overlaps MMAs) ----
        {
            int ntile = tile + gridDim.x;
            x0 = x1 = x2 = vld = 0.f;
            if (ntile < NTILES) {
                int px = ntile*128 + p;
                x0 = pc[px]; x1 = pc[NPOS + px]; x2 = pc[2*NPOS + px];
                if (t < 128) vld = valid[ntile*128 + t];
            }
        }

        // ---- layer 2: acc2[pos16][out2 64] per warp ----
        float acc2[8][4];
        #pragma unroll
        for (int nt = 0; nt < 8; ++nt) {
            float2 bb = *reinterpret_cast<const float2*>(&s_c2[nt*8 + qc]);
            acc2[nt][0] = bb.x; acc2[nt][1] = bb.y;
            acc2[nt][2] = bb.x; acc2[nt][3] = bb.y;
        }
        {
            const u32 a2b = y1b + a2off;
            #pragma unroll
            for (int kt = 0; kt < 4; ++kt) {
                u32 a[4];
                ldm4(a[0], a[1], a[2], a[3], a2b + kt*32);
                #pragma unroll
                for (int np = 0; np < 4; ++np) {
                    u32 b[4];
                    ldm4(b[0], b[1], b[2], b[3], w2base + np*(16*RSTRIDE*2) + kt*32);
                    // x4 fill order: b0=(n0-7,k0-7) b1=(n8-15,k0-7) b2=(n0-7,k8-15) b3=(n8-15,k8-15)
                    mma16816(acc2[2*np],   a, b[0], b[2]);   // n block lo: {k0-7, k8-15}
                    mma16816(acc2[2*np+1], a, b[1], b[3]);   // n block hi
                }
            }
        }

        // ---- relu+pack acc2 -> layer3 B fragments (registers) ----
        u32 y2b[4][2][2];
        #pragma unroll
        for (int kt = 0; kt < 4; ++kt) {
            y2b[kt][0][0] = pack2(fmaxf(acc2[2*kt][0],   0.f), fmaxf(acc2[2*kt][1],   0.f));
            y2b[kt][0][1] = pack2(fmaxf(acc2[2*kt+1][0], 0.f), fmaxf(acc2[2*kt+1][1], 0.f));
            y2b[kt][1][0] = pack2(fmaxf(acc2[2*kt][2],   0.f), fmaxf(acc2[2*kt][3],   0.f));
            y2b[kt][1][1] = pack2(fmaxf(acc2[2*kt+1][2], 0.f), fmaxf(acc2[2*kt+1][3], 0.f));
        }

        // ---- layer 3: [out3 128][pos16] in 8 out-blocks ----
        {
            float2 v0 = *reinterpret_cast<const float2*>(&s_val[buf*128 + w*16 + qc]);
            float2 v1 = *reinterpret_cast<const float2*>(&s_val[buf*128 + w*16 + 8 + qc]);
            float* outb = out + (size_t)p0 + w*16;

            #pragma unroll
            for (int ob = 0; ob < 8; ++ob) {
                float bq0 = s_c3[ob*16 + qr];
                float bq8 = s_c3[ob*16 + qr + 8];
                float accA[4] = {bq0, bq0, bq8, bq8};   // pos 0..7 of warp block
                float accB[4] = {bq0, bq0, bq8, bq8};   // pos 8..15
                #pragma unroll
                for (int kt = 0; kt < 4; ++kt) {
                    u32 a[4];
                    ldm4(a[0], a[1], a[2], a[3], w3base + ob*(16*RSTRIDE*2) + kt*32);
                    mma16816(accA, a, y2b[kt][0][0], y2b[kt][0][1]);
                    mma16816(accB, a, y2b[kt][1][0], y2b[kt][1][1]);
                }
                const int c0i = ob*16 + qr;
                float2 o;
                o.x = fmaxf(accA[0], 0.f) * v0.x;  o.y = fmaxf(accA[1], 0.f) * v0.y;
                *reinterpret_cast<float2*>(outb + (size_t)c0i*NPOS + qc) = o;
                o.x = fmaxf(accA[2], 0.f) * v0.x;  o.y = fmaxf(accA[3], 0.f) * v0.y;
                *reinterpret_cast<float2*>(outb + (size_t)(c0i+8)*NPOS + qc) = o;
                o.x = fmaxf(accB[0], 0.f) * v1.x;  o.y = fmaxf(accB[1], 0.f) * v1.y;
                *reinterpret_cast<float2*>(outb + (size_t)c0i*NPOS + 8 + qc) = o;
                o.x = fmaxf(accB[2], 0.f) * v1.x;  o.y = fmaxf(accB[3], 0.f) * v1.y;
                *reinterpret_cast<float2*>(outb + (size_t)(c0i+8)*NPOS + 8 + qc) = o;
            }
        }
        // no trailing barrier: Y1/val double-buffered; the single barrier
        // after next tile's layer1 orders reuse.
    }
}

extern "C" void kernel_launch(void* const* d_in, const int* in_sizes, int n_in,
                              void* d_out, int out_size)
{
    (void)in_sizes; (void)n_in; (void)out_size;
    cudaFuncSetAttribute(pn_mma_kernel,
                         cudaFuncAttributeMaxDynamicSharedMemorySize, SMEM_TOTAL);
    pn_mma_kernel<<<NBLOCKS, THREADS, SMEM_TOTAL>>>(
        (const float*)d_in[0],  (const float*)d_in[1],
        (const float*)d_in[2],  (const float*)d_in[3],  (const float*)d_in[4],
        (const float*)d_in[5],  (const float*)d_in[6],  (const float*)d_in[7],
        (const float*)d_in[8],  (const float*)d_in[9],  (const float*)d_in[10],
        (const float*)d_in[11], (const float*)d_in[12], (const float*)d_in[13],
        (const float*)d_in[14], (const float*)d_in[15], (const float*)d_in[16],
        (const float*)d_in[17], (const float*)d_in[18], (const float*)d_in[19],
        (float*)d_out);
}

// round 7
// speedup vs baseline: 8.1735x; 1.1705x over previous
#include <cuda_runtime.h>
#include <cuda_fp16.h>
#include <cstdint>

typedef uint32_t u32;

#define NPOS    (4096*128)
#define TILE    256
#define NTILES  (NPOS/TILE)    // 2048
#define THREADS 256
#define NBLOCKS 296

#define RSTRIDE 72             // halves per row (144 B, ldmatrix conflict-free)

// ---- dynamic SMEM layout (bytes) ----
#define SM_W1F  0              // 64 x float4                  (1024)
#define SM_C2   1024           // 64 f                         (256)
#define SM_C3   1280           // 128 f                        (512)
#define SM_VAL  1792           // 2 x 256 f (double-buffered)  (2048)
#define SM_Y1   3840           // 2 x 256 x 72 halves          (73728)
#define SM_W2   77568          // 64  x 72 halves              (9216)
#define SM_W3   86784          // 128 x 72 halves              (18432)
#define SMEM_TOTAL 105216
#define Y1_BUF  36864

static __device__ __forceinline__ u32 sptr(const void* p) {
    u32 a;
    asm("{ .reg .u64 t; cvta.to.shared.u64 t, %1; cvt.u32.u64 %0, t; }" : "=r"(a) : "l"(p));
    return a;
}
static __device__ __forceinline__ void ldm4(u32& r0, u32& r1, u32& r2, u32& r3, u32 addr) {
    asm volatile("ldmatrix.sync.aligned.m8n8.x4.shared.b16 {%0,%1,%2,%3}, [%4];"
                 : "=r"(r0), "=r"(r1), "=r"(r2), "=r"(r3) : "r"(addr));
}
static __device__ __forceinline__ void mma16816(float c[4], const u32 a[4], u32 b0, u32 b1) {
    asm volatile("mma.sync.aligned.m16n8k16.row.col.f32.f16.f16.f32 "
                 "{%0,%1,%2,%3}, {%4,%5,%6,%7}, {%8,%9}, {%0,%1,%2,%3};"
                 : "+f"(c[0]), "+f"(c[1]), "+f"(c[2]), "+f"(c[3])
                 : "r"(a[0]), "r"(a[1]), "r"(a[2]), "r"(a[3]), "r"(b0), "r"(b1));
}
static __device__ __forceinline__ u32 pack2(float a, float b) {
    __half2 h = __floats2half2_rn(a, b);
    return *reinterpret_cast<u32*>(&h);
}

extern "C" __global__ void __launch_bounds__(THREADS, 2)
pn_mma_kernel(const float* __restrict__ pc,  const float* __restrict__ valid,
              const float* __restrict__ W1,  const float* __restrict__ b1,
              const float* __restrict__ g1,  const float* __restrict__ be1,
              const float* __restrict__ m1,  const float* __restrict__ v1,
              const float* __restrict__ W2,  const float* __restrict__ b2,
              const float* __restrict__ g2,  const float* __restrict__ be2,
              const float* __restrict__ m2,  const float* __restrict__ v2,
              const float* __restrict__ W3,  const float* __restrict__ b3,
              const float* __restrict__ g3,  const float* __restrict__ be3,
              const float* __restrict__ m3,  const float* __restrict__ v3,
              float* __restrict__ out)
{
    extern __shared__ char smem[];
    const u32 sb = sptr(smem);
    const int t    = threadIdx.x;
    const int lane = t & 31;
    const int w    = t >> 5;

    float*  s_w1f = reinterpret_cast<float*>(smem + SM_W1F);
    float*  s_c2  = reinterpret_cast<float*>(smem + SM_C2);
    float*  s_c3  = reinterpret_cast<float*>(smem + SM_C3);
    float*  s_val = reinterpret_cast<float*>(smem + SM_VAL);
    __half* s_w2  = reinterpret_cast<__half*>(smem + SM_W2);
    __half* s_w3  = reinterpret_cast<__half*>(smem + SM_W3);

    // ---- one-time prep: fold BN, convert weights to fp16 ----
    if (t < 64) {
        float inv1 = g1[t] * rsqrtf(v1[t] + 1e-5f);
        s_w1f[4*t+0] = W1[3*t+0]*inv1;
        s_w1f[4*t+1] = W1[3*t+1]*inv1;
        s_w1f[4*t+2] = W1[3*t+2]*inv1;
        s_w1f[4*t+3] = be1[t] + (b1[t] - m1[t]) * inv1;
        float inv2 = g2[t] * rsqrtf(v2[t] + 1e-5f);
        s_c2[t] = be2[t] + (b2[t] - m2[t]) * inv2;
    }
    if (t < 128) {
        float inv3 = g3[t] * rsqrtf(v3[t] + 1e-5f);
        s_c3[t] = be3[t] + (b3[t] - m3[t]) * inv3;
    }
    for (int i = t; i < 64*64; i += THREADS) {
        int n = i >> 6, k = i & 63;
        float inv2 = g2[n] * rsqrtf(v2[n] + 1e-5f);
        s_w2[n*RSTRIDE + k] = __float2half_rn(W2[i] * inv2);
    }
    for (int i = t; i < 128*64; i += THREADS) {
        int n = i >> 6, k = i & 63;
        float inv3 = g3[n] * rsqrtf(v3[n] + 1e-5f);
        s_w3[n*RSTRIDE + k] = __float2half_rn(W3[i] * inv3);
    }
    __syncthreads();

    // ---- per-thread fragment geometry ----
    const int qr  = lane >> 2;                            // accum row in 8
    const int qc  = (lane & 3) * 2;                       // accum col pair
    const int lr8 = (lane & 7) + ((lane >> 3) & 1) * 8;   // ldm4 row-in-16
    const int lc8 = (lane >> 4) * 8;                      // ldm4 k offset

    const u32 w2base = sb + SM_W2 + (u32)(((lane & 15)*RSTRIDE + lc8)*2);
    const u32 w3base = sb + SM_W3 + (u32)((lr8*RSTRIDE + lc8)*2);
    const u32 a2off0 = (u32)(((w*32 +      lr8)*RSTRIDE + lc8)*2);
    const u32 a2off1 = (u32)(((w*32 + 16 + lr8)*RSTRIDE + lc8)*2);
    const u32 y1off  = (u32)(t * RSTRIDE * 2);            // layer1: one pos per thread

    // ---- prefetch first tile ----
    int tile = blockIdx.x;
    float x0 = 0.f, x1 = 0.f, x2 = 0.f, vld = 0.f;
    if (tile < NTILES) {
        int px = tile*TILE + t;
        x0 = pc[px]; x1 = pc[NPOS + px]; x2 = pc[2*NPOS + px];
        vld = valid[px];
    }

    int it = 0;
    for (; tile < NTILES; tile += gridDim.x, ++it) {
        const int p0  = tile * TILE;
        const int buf = it & 1;
        const u32 y1b = sb + SM_Y1 + (u32)buf * Y1_BUF;

        // ---- layer 1: fp32 -> relu -> fp16 Y1[pos][k] (one pos / thread) ----
        {
            s_val[buf*TILE + t] = vld;
            const u32 dst = y1b + y1off;
            #pragma unroll
            for (int cb = 0; cb < 64; cb += 8) {
                u32 pk[4];
                #pragma unroll
                for (int q = 0; q < 4; ++q) {
                    int c0i = cb + 2*q;
                    float ya = fmaf(s_w1f[4*c0i+0], x0, fmaf(s_w1f[4*c0i+1], x1,
                               fmaf(s_w1f[4*c0i+2], x2, s_w1f[4*c0i+3])));
                    float yb = fmaf(s_w1f[4*c0i+4], x0, fmaf(s_w1f[4*c0i+5], x1,
                               fmaf(s_w1f[4*c0i+6], x2, s_w1f[4*c0i+7])));
                    pk[q] = pack2(fmaxf(ya, 0.f), fmaxf(yb, 0.f));
                }
                asm volatile("st.shared.v4.b32 [%0], {%1,%2,%3,%4};"
                             :: "r"(dst + cb*2), "r"(pk[0]), "r"(pk[1]), "r"(pk[2]), "r"(pk[3])
                             : "memory");
            }
        }
        __syncthreads();

        // ---- prefetch next tile (overlaps MMAs) ----
        {
            int ntile = tile + gridDim.x;
            x0 = x1 = x2 = vld = 0.f;
            if (ntile < NTILES) {
                int px = ntile*TILE + t;
                x0 = pc[px]; x1 = pc[NPOS + px]; x2 = pc[2*NPOS + px];
                vld = valid[px];
            }
        }

        // ---- layer 2: acc2[pb 2][nt 8][4], two pos blocks share each W2 frag ----
        float acc2[2][8][4];
        #pragma unroll
        for (int nt = 0; nt < 8; ++nt) {
            float2 bb = *reinterpret_cast<const float2*>(&s_c2[nt*8 + qc]);
            #pragma unroll
            for (int pb = 0; pb < 2; ++pb) {
                acc2[pb][nt][0] = bb.x; acc2[pb][nt][1] = bb.y;
                acc2[pb][nt][2] = bb.x; acc2[pb][nt][3] = bb.y;
            }
        }
        {
            const u32 a2b0 = y1b + a2off0;
            const u32 a2b1 = y1b + a2off1;
            #pragma unroll
            for (int kt = 0; kt < 4; ++kt) {
                u32 aA[4], aB[4];
                ldm4(aA[0], aA[1], aA[2], aA[3], a2b0 + kt*32);
                ldm4(aB[0], aB[1], aB[2], aB[3], a2b1 + kt*32);
                #pragma unroll
                for (int np = 0; np < 4; ++np) {
                    u32 b[4];
                    ldm4(b[0], b[1], b[2], b[3], w2base + np*(16*RSTRIDE*2) + kt*32);
                    // x4 fill: b0=(n0-7,k0-7) b1=(n8-15,k0-7) b2=(n0-7,k8-15) b3=(n8-15,k8-15)
                    mma16816(acc2[0][2*np],   aA, b[0], b[2]);
                    mma16816(acc2[0][2*np+1], aA, b[1], b[3]);
                    mma16816(acc2[1][2*np],   aB, b[0], b[2]);
                    mma16816(acc2[1][2*np+1], aB, b[1], b[3]);
                }
            }
        }

        // ---- relu+pack acc2 -> layer3 B fragments (registers) ----
        u32 y2b[2][4][2][2];
        #pragma unroll
        for (int pb = 0; pb < 2; ++pb)
            #pragma unroll
            for (int kt = 0; kt < 4; ++kt) {
                y2b[pb][kt][0][0] = pack2(fmaxf(acc2[pb][2*kt][0],   0.f), fmaxf(acc2[pb][2*kt][1],   0.f));
                y2b[pb][kt][0][1] = pack2(fmaxf(acc2[pb][2*kt+1][0], 0.f), fmaxf(acc2[pb][2*kt+1][1], 0.f));
                y2b[pb][kt][1][0] = pack2(fmaxf(acc2[pb][2*kt][2],   0.f), fmaxf(acc2[pb][2*kt][3],   0.f));
                y2b[pb][kt][1][1] = pack2(fmaxf(acc2[pb][2*kt+1][2], 0.f), fmaxf(acc2[pb][2*kt+1][3], 0.f));
            }

        // ---- layer 3: [out3 128][pos 32] per warp, W3 frag shared by 4 MMAs ----
        {
            float2 vv[2][2];
            #pragma unroll
            for (int pb = 0; pb < 2; ++pb) {
                vv[pb][0] = *reinterpret_cast<const float2*>(&s_val[buf*TILE + w*32 + pb*16 + qc]);
                vv[pb][1] = *reinterpret_cast<const float2*>(&s_val[buf*TILE + w*32 + pb*16 + 8 + qc]);
            }
            float* outb = out + (size_t)p0 + w*32;

            #pragma unroll
            for (int ob = 0; ob < 8; ++ob) {
                float bq0 = s_c3[ob*16 + qr];
                float bq8 = s_c3[ob*16 + qr + 8];
                float acc[2][2][4];
                #pragma unroll
                for (int pb = 0; pb < 2; ++pb)
                    #pragma unroll
                    for (int h = 0; h < 2; ++h) {
                        acc[pb][h][0] = bq0; acc[pb][h][1] = bq0;
                        acc[pb][h][2] = bq8; acc[pb][h][3] = bq8;
                    }
                #pragma unroll
                for (int kt = 0; kt < 4; ++kt) {
                    u32 a[4];
                    ldm4(a[0], a[1], a[2], a[3], w3base + ob*(16*RSTRIDE*2) + kt*32);
                    mma16816(acc[0][0], a, y2b[0][kt][0][0], y2b[0][kt][0][1]);
                    mma16816(acc[0][1], a, y2b[0][kt][1][0], y2b[0][kt][1][1]);
                    mma16816(acc[1][0], a, y2b[1][kt][0][0], y2b[1][kt][0][1]);
                    mma16816(acc[1][1], a, y2b[1][kt][1][0], y2b[1][kt][1][1]);
                }
                const int c0i = ob*16 + qr;
                #pragma unroll
                for (int pb = 0; pb < 2; ++pb)
                    #pragma unroll
                    for (int h = 0; h < 2; ++h) {
                        const int pcol = pb*16 + h*8 + qc;
                        float2 o;
                        o.x = fmaxf(acc[pb][h][0], 0.f) * vv[pb][h].x;
                        o.y = fmaxf(acc[pb][h][1], 0.f) * vv[pb][h].y;
                        *reinterpret_cast<float2*>(outb + (size_t)c0i*NPOS + pcol) = o;
                        o.x = fmaxf(acc[pb][h][2], 0.f) * vv[pb][h].x;
                        o.y = fmaxf(acc[pb][h][3], 0.f) * vv[pb][h].y;
                        *reinterpret_cast<float2*>(outb + (size_t)(c0i+8)*NPOS + pcol) = o;
                    }
            }
        }
        // no trailing barrier: Y1/val double-buffered
    }
}

extern "C" void kernel_launch(void* const* d_in, const int* in_sizes, int n_in,
                              void* d_out, int out_size)
{
    (void)in_sizes; (void)n_in; (void)out_size;
    cudaFuncSetAttribute(pn_mma_kernel,
                         cudaFuncAttributeMaxDynamicSharedMemorySize, SMEM_TOTAL);
    pn_mma_kernel<<<NBLOCKS, THREADS, SMEM_TOTAL>>>(
        (const float*)d_in[0],  (const float*)d_in[1],
        (const float*)d_in[2],  (const float*)d_in[3],  (const float*)d_in[4],
        (const float*)d_in[5],  (const float*)d_in[6],  (const float*)d_in[7],
        (const float*)d_in[8],  (const float*)d_in[9],  (const float*)d_in[10],
        (const float*)d_in[11], (const float*)d_in[12], (const float*)d_in[13],
        (const float*)d_in[14], (const float*)d_in[15], (const float*)d_in[16],
        (const float*)d_in[17], (const float*)d_in[18], (const float*)d_in[19],
        (float*)d_out);
}